// round 5
// baseline (speedup 1.0000x reference)
#include <cuda_runtime.h>
#include <cuda_fp16.h>
#include <cstdint>

// ---------------- scratch ----------------
__device__ __align__(1024) __half g_bhalf[524288]; // [16 heads][512 k][64 n] fp16
__device__ float g_dot[2097152];                   // [b][n][s]
__device__ float g_wq[8192];                       // [c][n]

// ---------------- helpers ----------------
__device__ __forceinline__ uint32_t smem_u32(const void* p) {
    uint32_t a; asm("{ .reg .u64 t; cvta.to.shared.u64 t, %1; cvt.u32.u64 %0, t; }" : "=r"(a) : "l"(p));
    return a;
}
__device__ __forceinline__ uint32_t h2u(__half2 h) { return *reinterpret_cast<uint32_t*>(&h); }
__device__ __forceinline__ float tanh_fast(float x) {
    float e; asm("ex2.approx.f32 %0, %1;" : "=f"(e) : "f"(x * 2.885390082f));
    float r; asm("rcp.approx.f32 %0, %1;" : "=f"(r) : "f"(e + 1.0f));
    return fmaf(-2.0f, r, 1.0f);
}
#define CPASYNC16(dst, src) asm volatile( \
    "cp.async.cg.shared.global [%0], [%1], 16;" :: "r"(dst), "l"(src) : "memory")
#define CPCOMMIT() asm volatile("cp.async.commit_group;" ::: "memory")
#define CPWAIT1()  asm volatile("cp.async.wait_group 1;" ::: "memory")

__device__ __forceinline__ void ldsm4(uint32_t* r, uint32_t a) {
    asm volatile("ldmatrix.sync.aligned.m8n8.x4.shared.b16 {%0,%1,%2,%3}, [%4];"
        : "=r"(r[0]), "=r"(r[1]), "=r"(r[2]), "=r"(r[3]) : "r"(a));
}
__device__ __forceinline__ void ldsm4t(uint32_t* r, uint32_t a) {
    asm volatile("ldmatrix.sync.aligned.m8n8.x4.trans.shared.b16 {%0,%1,%2,%3}, [%4];"
        : "=r"(r[0]), "=r"(r[1]), "=r"(r[2]), "=r"(r[3]) : "r"(a));
}
__device__ __forceinline__ void mma16816(float* d, const uint32_t* a, uint32_t b0, uint32_t b1) {
    asm volatile("mma.sync.aligned.m16n8k16.row.col.f32.f16.f16.f32 "
        "{%0,%1,%2,%3}, {%4,%5,%6,%7}, {%8,%9}, {%0,%1,%2,%3};"
        : "+f"(d[0]), "+f"(d[1]), "+f"(d[2]), "+f"(d[3])
        : "r"(a[0]), "r"(a[1]), "r"(a[2]), "r"(a[3]), "r"(b0), "r"(b1));
}

// ---------------- K0a: wq[c][n] ----------------
__global__ void k0a(const float* __restrict__ Wk, const float* __restrict__ q) {
    int id = blockIdx.x * 256 + threadIdx.x;
    int c = id >> 4, n = id & 15;
    float a = 0.f;
    #pragma unroll 8
    for (int k = 0; k < 64; k++) a += Wk[(size_t)c * 1024 + n * 64 + k] * q[n * 64 + k];
    g_wq[c * 16 + n] = a;
}

// ---------------- K0b: W_v -> fp16 [head][k][64] ----------------
__global__ void k0b(const float* __restrict__ Wv) {
    int id = blockIdx.x * 256 + threadIdx.x;        // 524288
    int h = id >> 15, k = (id >> 6) & 511, n = id & 63;
    g_bhalf[id] = __float2half_rn(Wv[(size_t)k * 1024 + h * 64 + n]);
}

// ---------------- K1: dot[b][n][s] = x[b,s,:] . wq[:,n] ----------------
__global__ __launch_bounds__(256) void k1(const float* __restrict__ x) {
    __shared__ float swq[8192];
    int blk = blockIdx.x, b = blk >> 5, st = blk & 31;
    int t = threadIdx.x, w = t >> 5, l = t & 31;
    for (int i = t; i < 8192; i += 256) swq[i] = g_wq[i];
    __syncthreads();
    for (int rr = 0; rr < 16; rr++) {
        int row = w * 16 + rr;
        const float4* xr = (const float4*)(x + (size_t)(b * 4096 + st * 128 + row) * 512);
        float acc[16];
        #pragma unroll
        for (int n = 0; n < 16; n++) acc[n] = 0.f;
        #pragma unroll
        for (int j = 0; j < 4; j++) {
            float4 xv = xr[l + j * 32];
            int c = 4 * l + 128 * j;
            #pragma unroll
            for (int e = 0; e < 4; e++) {
                float xe = (&xv.x)[e];
                const float4* wr = (const float4*)(swq + (c + e) * 16);
                float4 w0 = wr[0], w1 = wr[1], w2 = wr[2], w3 = wr[3];
                acc[0]  = fmaf(xe, w0.x, acc[0]);   acc[1]  = fmaf(xe, w0.y, acc[1]);
                acc[2]  = fmaf(xe, w0.z, acc[2]);   acc[3]  = fmaf(xe, w0.w, acc[3]);
                acc[4]  = fmaf(xe, w1.x, acc[4]);   acc[5]  = fmaf(xe, w1.y, acc[5]);
                acc[6]  = fmaf(xe, w1.z, acc[6]);   acc[7]  = fmaf(xe, w1.w, acc[7]);
                acc[8]  = fmaf(xe, w2.x, acc[8]);   acc[9]  = fmaf(xe, w2.y, acc[9]);
                acc[10] = fmaf(xe, w2.z, acc[10]);  acc[11] = fmaf(xe, w2.w, acc[11]);
                acc[12] = fmaf(xe, w3.x, acc[12]);  acc[13] = fmaf(xe, w3.y, acc[13]);
                acc[14] = fmaf(xe, w3.z, acc[14]);  acc[15] = fmaf(xe, w3.w, acc[15]);
            }
        }
        #pragma unroll
        for (int o = 16; o; o >>= 1)
            #pragma unroll
            for (int n = 0; n < 16; n++) acc[n] += __shfl_xor_sync(~0u, acc[n], o);
        if (l == 0) {
            int sg = st * 128 + row;
            #pragma unroll
            for (int n = 0; n < 16; n++) g_dot[(size_t)(b * 16 + n) * 4096 + sg] = acc[n];
        }
    }
}

// ---------------- K2: softmax over s per (b,n); zero out ----------------
__global__ void k2(float* __restrict__ out) {
    __shared__ float red[8];
    int t = threadIdx.x;
    if (t < 64) out[blockIdx.x * 64 + t] = 0.f;
    float* p = g_dot + (size_t)blockIdx.x * 4096;
    float v[16], m = -1e30f;
    #pragma unroll
    for (int i = 0; i < 16; i++) { v[i] = p[t + i * 256]; m = fmaxf(m, v[i]); }
    #pragma unroll
    for (int o = 16; o; o >>= 1) m = fmaxf(m, __shfl_xor_sync(~0u, m, o));
    if ((t & 31) == 0) red[t >> 5] = m;
    __syncthreads();
    float M = red[0];
    #pragma unroll
    for (int i = 1; i < 8; i++) M = fmaxf(M, red[i]);
    float s = 0.f;
    #pragma unroll
    for (int i = 0; i < 16; i++) { v[i] = __expf(v[i] - M); s += v[i]; }
    #pragma unroll
    for (int o = 16; o; o >>= 1) s += __shfl_xor_sync(~0u, s, o);
    __syncthreads();
    if ((t & 31) == 0) red[t >> 5] = s;
    __syncthreads();
    float S = 0.f;
    #pragma unroll
    for (int i = 0; i < 8; i++) S += red[i];
    float inv = 1.0f / S;
    #pragma unroll
    for (int i = 0; i < 16; i++) p[t + i * 256] = v[i] * inv;
}

// ---------------- K3: value GEMM (mma.sync f16) + tanh + attn-reduce ----------------
// smem layout (bytes): A 0..133120 (128 x 520 halfs), B0 133120, B1 169984
// (each 256 x 72 halfs = 36864), bias 206848..210944, sred 210944..211968
#define SM_A    0
#define SM_B0   133120
#define SM_BS   36864
#define SM_BIAS 206848
#define SM_RED  210944
#define K3_DYN  211968
#define ASTRIDE 1040      // bytes per A row (520 halfs)
#define BSTRIDE 144       // bytes per B row (72 halfs)

__global__ __launch_bounds__(256, 1) void k3(const float* __restrict__ x,
                                             const float* __restrict__ bv,
                                             float* __restrict__ out) {
    extern __shared__ char sm[];
    uint32_t sb = smem_u32(sm);
    int t = threadIdx.x, wid = t >> 5, l = t & 31;
    int blk = blockIdx.x, b = blk >> 5, st = blk & 31;
    int rb = wid & 3, cb = wid >> 2;                 // row-block (32 rows), col-block (32 cols)
    float* sbias = (float*)(sm + SM_BIAS);
    float* sred  = (float*)(sm + SM_RED);

    // prefetch head0 chunks 0,1 (each: 256 k-rows x 128B -> padded smem rows)
    {
        const char* src = (const char*)g_bhalf + (size_t)t * 128;
        uint32_t dst = sb + SM_B0 + t * BSTRIDE;
        #pragma unroll
        for (int i = 0; i < 8; i++) CPASYNC16(dst + i * 16, src + i * 16);
        CPCOMMIT();
        src += 256 * 128;
        dst = sb + SM_B0 + SM_BS + t * BSTRIDE;
        #pragma unroll
        for (int i = 0; i < 8; i++) CPASYNC16(dst + i * 16, src + i * 16);
        CPCOMMIT();
    }

    // A tile: convert fp32 -> fp16 rows (stride 520 halfs)
    {
        int r = t >> 1, hf = t & 1;
        const float4* xr = (const float4*)(x + (size_t)(b * 4096 + st * 128 + r) * 512 + hf * 256);
        char* arow = sm + SM_A + r * ASTRIDE + hf * 512;
        #pragma unroll 4
        for (int i = 0; i < 32; i++) {
            float4 f0 = xr[2 * i], f1 = xr[2 * i + 1];
            uint4 u;
            u.x = h2u(__floats2half2_rn(f0.x, f0.y));
            u.y = h2u(__floats2half2_rn(f0.z, f0.w));
            u.z = h2u(__floats2half2_rn(f1.x, f1.y));
            u.w = h2u(__floats2half2_rn(f1.z, f1.w));
            *(uint4*)(arow + i * 16) = u;
        }
    }
    for (int i = t; i < 1024; i += 256) sbias[i] = bv[i];
    __syncthreads();

    // per-lane ldmatrix base addresses
    uint32_t a_base0 = sb + SM_A + (rb * 32 + 0  + (l & 7) + 8 * ((l >> 3) & 1)) * ASTRIDE + (l >> 4) * 16;
    uint32_t a_base1 = sb + SM_A + (rb * 32 + 16 + (l & 7) + 8 * ((l >> 3) & 1)) * ASTRIDE + (l >> 4) * 16;
    uint32_t b_lane  = ((l & 7) + 8 * ((l >> 3) & 1)) * BSTRIDE + (cb * 32 + 8 * (l >> 4)) * 2;

    float acc[2][4][4];

    for (int i = 0; i < 32; i++) {
        int h = i >> 1, ch = i & 1;
        uint32_t bbuf = sb + SM_B0 + (i & 1) * SM_BS;
        CPWAIT1();
        __syncthreads();
        if (ch == 0) {
            #pragma unroll
            for (int m = 0; m < 2; m++)
                #pragma unroll
                for (int n = 0; n < 4; n++)
                    #pragma unroll
                    for (int e = 0; e < 4; e++) acc[m][n][e] = 0.f;
        }
        #pragma unroll 4
        for (int kk = 0; kk < 16; kk++) {
            uint32_t a0[4], a1[4], bf0[4], bf1[4];
            uint32_t ko = ch * 512 + kk * 32;       // A col byte offset
            ldsm4(a0, a_base0 + ko);
            ldsm4(a1, a_base1 + ko);
            uint32_t brow = bbuf + b_lane + kk * 16 * BSTRIDE;
            ldsm4t(bf0, brow);
            ldsm4t(bf1, brow + 32);
            #pragma unroll
            for (int n = 0; n < 2; n++) {
                mma16816(acc[0][n],     a0, bf0[2 * n], bf0[2 * n + 1]);
                mma16816(acc[1][n],     a1, bf0[2 * n], bf0[2 * n + 1]);
                mma16816(acc[0][n + 2], a0, bf1[2 * n], bf1[2 * n + 1]);
                mma16816(acc[1][n + 2], a1, bf1[2 * n], bf1[2 * n + 1]);
            }
        }
        __syncthreads();   // all warps done reading this B buffer
        if (i + 2 < 32) {  // prefetch (head,chunk) i+2 into the buffer just freed
            const char* src = (const char*)g_bhalf + (size_t)(i + 2) * 256 * 128 + (size_t)t * 128;
            uint32_t dst = sb + SM_B0 + (i & 1) * SM_BS + t * BSTRIDE;
            #pragma unroll
            for (int j = 0; j < 8; j++) CPASYNC16(dst + j * 16, src + j * 16);
        }
        CPCOMMIT();

        if (ch == 1) {  // epilogue for head h
            const float* ap = g_dot + (size_t)(b * 16 + h) * 4096 + st * 128 + rb * 32 + (l >> 2);
            float s0[4], s1[4];
            #pragma unroll
            for (int n = 0; n < 4; n++) { s0[n] = 0.f; s1[n] = 0.f; }
            #pragma unroll
            for (int m = 0; m < 2; m++) {
                float aA = ap[16 * m], aB = ap[16 * m + 8];
                #pragma unroll
                for (int n = 0; n < 4; n++) {
                    int c0 = cb * 32 + 8 * n + 2 * (l & 3);
                    float b0 = sbias[h * 64 + c0], b1 = sbias[h * 64 + c0 + 1];
                    s0[n] += aA * tanh_fast(acc[m][n][0] + b0) + aB * tanh_fast(acc[m][n][2] + b0);
                    s1[n] += aA * tanh_fast(acc[m][n][1] + b1) + aB * tanh_fast(acc[m][n][3] + b1);
                }
            }
            #pragma unroll
            for (int o = 4; o < 32; o <<= 1)
                #pragma unroll
                for (int n = 0; n < 4; n++) {
                    s0[n] += __shfl_xor_sync(~0u, s0[n], o);
                    s1[n] += __shfl_xor_sync(~0u, s1[n], o);
                }
            if (l < 4) {
                #pragma unroll
                for (int n = 0; n < 4; n++) {
                    sred[wid * 32 + 8 * n + 2 * l]     = s0[n];
                    sred[wid * 32 + 8 * n + 2 * l + 1] = s1[n];
                }
            }
            __syncthreads();
            if (t < 64) {
                int cw = t >> 5, cc = t & 31;
                float s = sred[(cw * 4 + 0) * 32 + cc] + sred[(cw * 4 + 1) * 32 + cc]
                        + sred[(cw * 4 + 2) * 32 + cc] + sred[(cw * 4 + 3) * 32 + cc];
                atomicAdd(&out[b * 1024 + h * 64 + t], s);
            }
        }
    }
}

// ---------------- launch ----------------
extern "C" void kernel_launch(void* const* d_in, const int* in_sizes, int n_in,
                              void* d_out, int out_size) {
    const float* kv = (const float*)d_in[0];
    const float* Wk = (const float*)d_in[1];
    const float* Wv = (const float*)d_in[3];
    const float* bv = (const float*)d_in[4];
    const float* q  = (const float*)d_in[5];
    float* out = (float*)d_out;
    cudaFuncSetAttribute(k3, cudaFuncAttributeMaxDynamicSharedMemorySize, K3_DYN);
    k0a<<<32, 256>>>(Wk, q);
    k0b<<<2048, 256>>>(Wv);
    k1<<<1024, 256>>>(kv);
    k2<<<512, 256>>>(out);
    k3<<<1024, 256, K3_DYN>>>(kv, bv, out);
}

// round 6
// speedup vs baseline: 1.1228x; 1.1228x over previous
#include <cuda_runtime.h>
#include <cuda_fp16.h>
#include <cstdint>

// ---------------- scratch ----------------
__device__ __align__(1024) __half g_ximg[67108864]; // [b][s][512] fp16 x image (134MB)
__device__ __align__(1024) __half g_bhalf[524288];  // [16 heads][512 k][64 n] fp16
__device__ float g_dot[2097152];                    // [b][n][s]
__device__ float g_wq[8192];                        // [c][n]

// ---------------- helpers ----------------
__device__ __forceinline__ uint32_t smem_u32(const void* p) {
    uint32_t a; asm("{ .reg .u64 t; cvta.to.shared.u64 t, %1; cvt.u32.u64 %0, t; }" : "=r"(a) : "l"(p));
    return a;
}
__device__ __forceinline__ uint32_t h2u(__half2 h) { return *reinterpret_cast<uint32_t*>(&h); }
__device__ __forceinline__ float tanh_fast(float x) {
    float e; asm("ex2.approx.f32 %0, %1;" : "=f"(e) : "f"(x * 2.885390082f));
    float r; asm("rcp.approx.f32 %0, %1;" : "=f"(r) : "f"(e + 1.0f));
    return fmaf(-2.0f, r, 1.0f);
}
#define CPASYNC16(dst, src) asm volatile( \
    "cp.async.cg.shared.global [%0], [%1], 16;" :: "r"(dst), "l"(src) : "memory")
#define CPCOMMIT() asm volatile("cp.async.commit_group;" ::: "memory")
#define CPWAIT1()  asm volatile("cp.async.wait_group 1;" ::: "memory")
#define BARSYNC(id) asm volatile("bar.sync %0, 256;" :: "r"(id) : "memory")

__device__ __forceinline__ void ldsm4(uint32_t* r, uint32_t a) {
    asm volatile("ldmatrix.sync.aligned.m8n8.x4.shared.b16 {%0,%1,%2,%3}, [%4];"
        : "=r"(r[0]), "=r"(r[1]), "=r"(r[2]), "=r"(r[3]) : "r"(a));
}
__device__ __forceinline__ void ldsm4t(uint32_t* r, uint32_t a) {
    asm volatile("ldmatrix.sync.aligned.m8n8.x4.trans.shared.b16 {%0,%1,%2,%3}, [%4];"
        : "=r"(r[0]), "=r"(r[1]), "=r"(r[2]), "=r"(r[3]) : "r"(a));
}
__device__ __forceinline__ void mma16816(float* d, const uint32_t* a, uint32_t b0, uint32_t b1) {
    asm volatile("mma.sync.aligned.m16n8k16.row.col.f32.f16.f16.f32 "
        "{%0,%1,%2,%3}, {%4,%5,%6,%7}, {%8,%9}, {%0,%1,%2,%3};"
        : "+f"(d[0]), "+f"(d[1]), "+f"(d[2]), "+f"(d[3])
        : "r"(a[0]), "r"(a[1]), "r"(a[2]), "r"(a[3]), "r"(b0), "r"(b1));
}

// ---------------- kz: zero out (also shifts ncu capture index onto k3) ----------------
__global__ void kz(float* __restrict__ out) {
    out[blockIdx.x * 256 + threadIdx.x] = 0.f;
}

// ---------------- K0a: wq[c][n] ----------------
__global__ void k0a(const float* __restrict__ Wk, const float* __restrict__ q) {
    int id = blockIdx.x * 256 + threadIdx.x;
    int c = id >> 4, n = id & 15;
    float a = 0.f;
    #pragma unroll 8
    for (int k = 0; k < 64; k++) a += Wk[(size_t)c * 1024 + n * 64 + k] * q[n * 64 + k];
    g_wq[c * 16 + n] = a;
}

// ---------------- K0b: W_v -> fp16 [head][k][64] ----------------
__global__ void k0b(const float* __restrict__ Wv) {
    int id = blockIdx.x * 256 + threadIdx.x;        // 524288
    int h = id >> 15, k = (id >> 6) & 511, n = id & 63;
    g_bhalf[id] = __float2half_rn(Wv[(size_t)k * 1024 + h * 64 + n]);
}

// ---------------- K1: dot[b][n][s] = x.wq ; also write fp16 x-image ----------------
__global__ __launch_bounds__(256) void k1(const float* __restrict__ x) {
    __shared__ float swq[8192];
    int blk = blockIdx.x, b = blk >> 5, st = blk & 31;
    int t = threadIdx.x, w = t >> 5, l = t & 31;
    for (int i = t; i < 8192; i += 256) swq[i] = g_wq[i];
    __syncthreads();
    for (int rr = 0; rr < 16; rr++) {
        int row = w * 16 + rr;
        size_t rbase = (size_t)(b * 4096 + st * 128 + row) * 512;
        const float4* xr = (const float4*)(x + rbase);
        char* irow = (char*)g_ximg + rbase * 2;
        float acc[16];
        #pragma unroll
        for (int n = 0; n < 16; n++) acc[n] = 0.f;
        #pragma unroll
        for (int j = 0; j < 4; j++) {
            float4 xv = xr[l + j * 32];
            int c = 4 * l + 128 * j;
            uint2 img;
            img.x = h2u(__floats2half2_rn(xv.x, xv.y));
            img.y = h2u(__floats2half2_rn(xv.z, xv.w));
            *(uint2*)(irow + c * 2) = img;
            #pragma unroll
            for (int e = 0; e < 4; e++) {
                float xe = (&xv.x)[e];
                const float4* wr = (const float4*)(swq + (c + e) * 16);
                float4 w0 = wr[0], w1 = wr[1], w2 = wr[2], w3 = wr[3];
                acc[0]  = fmaf(xe, w0.x, acc[0]);   acc[1]  = fmaf(xe, w0.y, acc[1]);
                acc[2]  = fmaf(xe, w0.z, acc[2]);   acc[3]  = fmaf(xe, w0.w, acc[3]);
                acc[4]  = fmaf(xe, w1.x, acc[4]);   acc[5]  = fmaf(xe, w1.y, acc[5]);
                acc[6]  = fmaf(xe, w1.z, acc[6]);   acc[7]  = fmaf(xe, w1.w, acc[7]);
                acc[8]  = fmaf(xe, w2.x, acc[8]);   acc[9]  = fmaf(xe, w2.y, acc[9]);
                acc[10] = fmaf(xe, w2.z, acc[10]);  acc[11] = fmaf(xe, w2.w, acc[11]);
                acc[12] = fmaf(xe, w3.x, acc[12]);  acc[13] = fmaf(xe, w3.y, acc[13]);
                acc[14] = fmaf(xe, w3.z, acc[14]);  acc[15] = fmaf(xe, w3.w, acc[15]);
            }
        }
        #pragma unroll
        for (int o = 16; o; o >>= 1)
            #pragma unroll
            for (int n = 0; n < 16; n++) acc[n] += __shfl_xor_sync(~0u, acc[n], o);
        if (l == 0) {
            int sg = st * 128 + row;
            #pragma unroll
            for (int n = 0; n < 16; n++) g_dot[(size_t)(b * 16 + n) * 4096 + sg] = acc[n];
        }
    }
}

// ---------------- K2: softmax over s per (b,n), in place ----------------
__global__ void k2() {
    __shared__ float red[8];
    int t = threadIdx.x;
    float* p = g_dot + (size_t)blockIdx.x * 4096;
    float v[16], m = -1e30f;
    #pragma unroll
    for (int i = 0; i < 16; i++) { v[i] = p[t + i * 256]; m = fmaxf(m, v[i]); }
    #pragma unroll
    for (int o = 16; o; o >>= 1) m = fmaxf(m, __shfl_xor_sync(~0u, m, o));
    if ((t & 31) == 0) red[t >> 5] = m;
    __syncthreads();
    float M = red[0];
    #pragma unroll
    for (int i = 1; i < 8; i++) M = fmaxf(M, red[i]);
    float s = 0.f;
    #pragma unroll
    for (int i = 0; i < 16; i++) { v[i] = __expf(v[i] - M); s += v[i]; }
    #pragma unroll
    for (int o = 16; o; o >>= 1) s += __shfl_xor_sync(~0u, s, o);
    __syncthreads();
    if ((t & 31) == 0) red[t >> 5] = s;
    __syncthreads();
    float S = 0.f;
    #pragma unroll
    for (int i = 0; i < 8; i++) S += red[i];
    float inv = 1.0f / S;
    #pragma unroll
    for (int i = 0; i < 16; i++) p[t + i * 256] = v[i] * inv;
}

// ---------------- K3: 16 warps, 2-way K-split, group-local barriers ----------------
// smem: A 0..133120 (128 x 1040B), B 133120..206848 (4 x 18432: [group][stage]),
// Y 206848..224256 (128 x 136B fp16), bias 224256..228352, sred 228352..229376
#define SM_A    0
#define SM_B    133120
#define SM_BCH  18432
#define SM_Y    206848
#define YSTR    136
#define SM_BIAS 224256
#define SM_RED  228352
#define K3_DYN  229376
#define ASTR    1040
#define BSTR    144

__global__ __launch_bounds__(512, 1) void k3(const float* __restrict__ bv,
                                             float* __restrict__ out) {
    extern __shared__ char sm[];
    uint32_t sb = smem_u32(sm);
    int t = threadIdx.x, wid = t >> 5, l = t & 31;
    int g = wid >> 3, w8 = wid & 7, rb = w8 & 3, cb = w8 >> 2;
    int blk = blockIdx.x, b = blk >> 5, st = blk & 31;
    float* sbias = (float*)(sm + SM_BIAS);
    float* sred  = (float*)(sm + SM_RED);
    int u = t & 255;

    // A load: each thread one quarter-row (16 x 16B)
    {
        const char* src = (const char*)g_ximg + (size_t)(b * 4096 + st * 128) * 1024;
        int r = t >> 2, q = t & 3;
        uint32_t dst = sb + SM_A + r * ASTR + q * 256;
        const char* s = src + r * 1024 + q * 256;
        #pragma unroll
        for (int j = 0; j < 16; j++) CPASYNC16(dst + j * 16, s + j * 16);
    }
    CPCOMMIT();
    // B prefetch: streams 0,1 of this group's k-range
    const char* bbase = (const char*)g_bhalf;
    {
        int row = u >> 1, hf = u & 1;
        #pragma unroll
        for (int c = 0; c < 2; c++) {
            const char* s = bbase + ((size_t)(g * 256 + c * 128 + row) * 64 + hf * 32) * 2;
            uint32_t d = sb + SM_B + (g * 2 + c) * SM_BCH + row * BSTR + hf * 64;
            #pragma unroll
            for (int j = 0; j < 4; j++) CPASYNC16(d + j * 16, s + j * 16);
            CPCOMMIT();
        }
    }
    for (int i = t; i < 1024; i += 512) sbias[i] = bv[i];

    uint32_t a_base = sb + SM_A + (rb * 32 + (l & 7) + 8 * ((l >> 3) & 1)) * ASTR
                    + (l >> 4) * 16 + g * 512;
    uint32_t b_lane = ((l & 7) + 8 * ((l >> 3) & 1)) * BSTR + (cb * 32 + 8 * (l >> 4)) * 2;
    int barid = 1 + g;
    float acc[2][4][4];

    for (int i = 0; i < 32; i++) {
        int h = i >> 1, c = i & 1;
        uint32_t bbuf = sb + SM_B + (g * 2 + c) * SM_BCH;
        CPWAIT1();
        if (i == 0) __syncthreads();   // A + bias visible CTA-wide
        else BARSYNC(barid);           // group's B chunk ready
        if (c == 0) {
            #pragma unroll
            for (int m = 0; m < 2; m++)
                #pragma unroll
                for (int n = 0; n < 4; n++)
                    #pragma unroll
                    for (int e = 0; e < 4; e++) acc[m][n][e] = 0.f;
        }
        #pragma unroll
        for (int kk = 0; kk < 8; kk++) {
            uint32_t a0[4], a1[4], bf0[4], bf1[4];
            uint32_t ko = c * 256 + kk * 32;
            ldsm4(a0, a_base + ko);
            ldsm4(a1, a_base + 16 * ASTR + ko);
            uint32_t brow = bbuf + b_lane + kk * 16 * BSTR;
            ldsm4t(bf0, brow);
            ldsm4t(bf1, brow + 32);
            #pragma unroll
            for (int n = 0; n < 2; n++) {
                mma16816(acc[0][n],     a0, bf0[2 * n], bf0[2 * n + 1]);
                mma16816(acc[1][n],     a1, bf0[2 * n], bf0[2 * n + 1]);
                mma16816(acc[0][n + 2], a0, bf1[2 * n], bf1[2 * n + 1]);
                mma16816(acc[1][n + 2], a1, bf1[2 * n], bf1[2 * n + 1]);
            }
        }
        BARSYNC(barid);                // group done reading buffer
        if (i + 2 < 32) {
            int i2 = i + 2, h2 = i2 >> 1, c2 = i2 & 1;
            int row = u >> 1, hf = u & 1;
            const char* s = bbase + ((size_t)(h2 * 512 + g * 256 + c2 * 128 + row) * 64 + hf * 32) * 2;
            uint32_t d = sb + SM_B + (g * 2 + c2) * SM_BCH + row * BSTR + hf * 64;
            #pragma unroll
            for (int j = 0; j < 4; j++) CPASYNC16(d + j * 16, s + j * 16);
        }
        CPCOMMIT();

        if (c == 1) {                  // end of head h
            __syncthreads();
            if (g == 1) {              // dump partial-y (fp16) for k in [256,512)
                #pragma unroll
                for (int m = 0; m < 2; m++) {
                    int rA = rb * 32 + 16 * m + (l >> 2);
                    #pragma unroll
                    for (int n = 0; n < 4; n++) {
                        int c0 = cb * 32 + 8 * n + 2 * (l & 3);
                        *(uint32_t*)(sm + SM_Y + rA * YSTR + c0 * 2) =
                            h2u(__floats2half2_rn(acc[m][n][0], acc[m][n][1]));
                        *(uint32_t*)(sm + SM_Y + (rA + 8) * YSTR + c0 * 2) =
                            h2u(__floats2half2_rn(acc[m][n][2], acc[m][n][3]));
                    }
                }
            }
            __syncthreads();
            if (g == 0) {              // combine + tanh + attn-reduce (B runs next MMA)
                const float* ap = g_dot + (size_t)(b * 16 + h) * 4096 + st * 128 + rb * 32 + (l >> 2);
                float s0[4], s1[4];
                #pragma unroll
                for (int n = 0; n < 4; n++) { s0[n] = 0.f; s1[n] = 0.f; }
                #pragma unroll
                for (int m = 0; m < 2; m++) {
                    int rA = rb * 32 + 16 * m + (l >> 2);
                    float aA = ap[16 * m], aB = ap[16 * m + 8];
                    #pragma unroll
                    for (int n = 0; n < 4; n++) {
                        int c0 = cb * 32 + 8 * n + 2 * (l & 3);
                        __half2 yA = *(const __half2*)(sm + SM_Y + rA * YSTR + c0 * 2);
                        __half2 yB = *(const __half2*)(sm + SM_Y + (rA + 8) * YSTR + c0 * 2);
                        float2 fA = __half22float2(yA), fB = __half22float2(yB);
                        float b0 = sbias[h * 64 + c0], b1 = sbias[h * 64 + c0 + 1];
                        s0[n] += aA * tanh_fast(acc[m][n][0] + fA.x + b0)
                               + aB * tanh_fast(acc[m][n][2] + fB.x + b0);
                        s1[n] += aA * tanh_fast(acc[m][n][1] + fA.y + b1)
                               + aB * tanh_fast(acc[m][n][3] + fB.y + b1);
                    }
                }
                #pragma unroll
                for (int o = 4; o < 32; o <<= 1)
                    #pragma unroll
                    for (int n = 0; n < 4; n++) {
                        s0[n] += __shfl_xor_sync(~0u, s0[n], o);
                        s1[n] += __shfl_xor_sync(~0u, s1[n], o);
                    }
                if (l < 4) {
                    #pragma unroll
                    for (int n = 0; n < 4; n++) {
                        sred[w8 * 32 + 8 * n + 2 * l]     = s0[n];
                        sred[w8 * 32 + 8 * n + 2 * l + 1] = s1[n];
                    }
                }
                BARSYNC(3);
                if (t < 64) {
                    int cw = t >> 5, cc = t & 31;
                    float s = sred[(cw * 4 + 0) * 32 + cc] + sred[(cw * 4 + 1) * 32 + cc]
                            + sred[(cw * 4 + 2) * 32 + cc] + sred[(cw * 4 + 3) * 32 + cc];
                    atomicAdd(&out[b * 1024 + h * 64 + t], s);
                }
            }
        }
    }
}

// ---------------- launch ----------------
extern "C" void kernel_launch(void* const* d_in, const int* in_sizes, int n_in,
                              void* d_out, int out_size) {
    const float* kv = (const float*)d_in[0];
    const float* Wk = (const float*)d_in[1];
    const float* Wv = (const float*)d_in[3];
    const float* bv = (const float*)d_in[4];
    const float* q  = (const float*)d_in[5];
    float* out = (float*)d_out;
    cudaFuncSetAttribute(k3, cudaFuncAttributeMaxDynamicSharedMemorySize, K3_DYN);
    kz<<<128, 256>>>(out);
    k0a<<<32, 256>>>(Wk, q);
    k0b<<<2048, 256>>>(Wv);
    k1<<<1024, 256>>>(kv);
    k2<<<512, 256>>>();
    k3<<<1024, 512, K3_DYN>>>(bv, out);
}

// round 7
// speedup vs baseline: 1.4419x; 1.2842x over previous
#include <cuda_runtime.h>
#include <cuda_fp16.h>
#include <cstdint>

// ---------------- scratch ----------------
__device__ __align__(1024) __half g_ximg[67108864]; // [b][s][512] fp16 x image
__device__ __align__(1024) __half g_bhalf[557056];  // [17 slots][512 k][64 n] fp16 (slot16 = wq)
__device__ float g_wq[8192];                        // [c][n]
__device__ float g_Z[512];                          // [b][n] softmax denominators

// ---------------- helpers ----------------
__device__ __forceinline__ uint32_t smem_u32(const void* p) {
    uint32_t a; asm("{ .reg .u64 t; cvta.to.shared.u64 t, %1; cvt.u32.u64 %0, t; }" : "=r"(a) : "l"(p));
    return a;
}
__device__ __forceinline__ uint32_t h2u(__half2 h) { return *reinterpret_cast<uint32_t*>(&h); }
__device__ __forceinline__ float tanh_fast(float x) {
    float e; asm("ex2.approx.f32 %0, %1;" : "=f"(e) : "f"(x * 2.885390082f));
    float r; asm("rcp.approx.f32 %0, %1;" : "=f"(r) : "f"(e + 1.0f));
    return fmaf(-2.0f, r, 1.0f);
}
__device__ __forceinline__ float exp_fast(float x) {
    float e; asm("ex2.approx.f32 %0, %1;" : "=f"(e) : "f"(x * 1.44269504f));
    return e;
}
#define CPASYNC16(dst, src) asm volatile( \
    "cp.async.cg.shared.global [%0], [%1], 16;" :: "r"(dst), "l"(src) : "memory")
#define CPCOMMIT() asm volatile("cp.async.commit_group;" ::: "memory")
#define CPWAIT1()  asm volatile("cp.async.wait_group 1;" ::: "memory")
#define BARSYNC(id)   asm volatile("bar.sync %0, 256;" :: "r"(id) : "memory")
#define BAR_ARRIVE4() asm volatile("bar.arrive 4, 512;" ::: "memory")
#define BAR_SYNC4()   asm volatile("bar.sync 4, 512;" ::: "memory")

__device__ __forceinline__ void ldsm4(uint32_t* r, uint32_t a) {
    asm volatile("ldmatrix.sync.aligned.m8n8.x4.shared.b16 {%0,%1,%2,%3}, [%4];"
        : "=r"(r[0]), "=r"(r[1]), "=r"(r[2]), "=r"(r[3]) : "r"(a));
}
__device__ __forceinline__ void ldsm4t(uint32_t* r, uint32_t a) {
    asm volatile("ldmatrix.sync.aligned.m8n8.x4.trans.shared.b16 {%0,%1,%2,%3}, [%4];"
        : "=r"(r[0]), "=r"(r[1]), "=r"(r[2]), "=r"(r[3]) : "r"(a));
}
__device__ __forceinline__ void mma16816(float* d, const uint32_t* a, uint32_t b0, uint32_t b1) {
    asm volatile("mma.sync.aligned.m16n8k16.row.col.f32.f16.f16.f32 "
        "{%0,%1,%2,%3}, {%4,%5,%6,%7}, {%8,%9}, {%0,%1,%2,%3};"
        : "+f"(d[0]), "+f"(d[1]), "+f"(d[2]), "+f"(d[3])
        : "r"(a[0]), "r"(a[1]), "r"(a[2]), "r"(a[3]), "r"(b0), "r"(b1));
}

// ---------------- kA: wq compute + zero out/g_Z ----------------
__global__ void kA(const float* __restrict__ Wk, const float* __restrict__ q,
                   float* __restrict__ out) {
    int blk = blockIdx.x, t = threadIdx.x;
    if (blk < 32) {
        int id = blk * 256 + t;
        int c = id >> 4, n = id & 15;
        float a = 0.f;
        #pragma unroll 8
        for (int k = 0; k < 64; k++) a += Wk[(size_t)c * 1024 + n * 64 + k] * q[n * 64 + k];
        g_wq[c * 16 + n] = a;
    } else {
        int id = (blk - 32) * 256 + t;
        if (id < 32768) out[id] = 0.f;
        else g_Z[id - 32768] = 0.f;
    }
}

// ---------------- kB: W_v + wq -> fp16 [17][512][64] ----------------
__global__ void kB(const float* __restrict__ Wv) {
    int id = blockIdx.x * 256 + threadIdx.x;     // 557056
    if (id < 524288) {
        int h = id >> 15, k = (id >> 6) & 511, n = id & 63;
        g_bhalf[id] = __float2half_rn(Wv[(size_t)k * 1024 + h * 64 + n]);
    } else {
        int j = id - 524288, k = j >> 6, n = j & 63;
        g_bhalf[id] = __float2half_rn(n < 16 ? g_wq[k * 16 + n] : 0.f);
    }
}

// ---------------- kconv: x fp32 -> fp16 image ----------------
__global__ __launch_bounds__(256) void kconv(const float* __restrict__ x) {
    size_t id = (size_t)blockIdx.x * 256 + threadIdx.x;   // 4194304
    const float4* s = (const float4*)(x + id * 16);
    float4 f0 = s[0], f1 = s[1], f2 = s[2], f3 = s[3];
    uint4 u0, u1;
    u0.x = h2u(__floats2half2_rn(f0.x, f0.y)); u0.y = h2u(__floats2half2_rn(f0.z, f0.w));
    u0.z = h2u(__floats2half2_rn(f1.x, f1.y)); u0.w = h2u(__floats2half2_rn(f1.z, f1.w));
    u1.x = h2u(__floats2half2_rn(f2.x, f2.y)); u1.y = h2u(__floats2half2_rn(f2.z, f2.w));
    u1.z = h2u(__floats2half2_rn(f3.x, f3.y)); u1.w = h2u(__floats2half2_rn(f3.z, f3.w));
    uint4* d = (uint4*)((char*)g_ximg + id * 32);
    d[0] = u0; d[1] = u1;
}

// ---------------- k3: 17-slot GEMM + inline softmax-weights + tanh reduce ----------------
// smem: A 0..133120 (128x1040B), B 133120..206848 (4x18432), Y 206848..224256 (128x136B),
// bias16 224256..226304, sred 226304..227328, sdot16 227328..231424, sZ 231424..231488
#define SM_A    0
#define SM_B    133120
#define SM_BCH  18432
#define SM_Y    206848
#define YSTR    136
#define SM_BIAS 224256
#define SM_RED  226304
#define SM_DOT  227328
#define SM_Z    231424
#define K3_DYN  231488
#define ASTR    1040
#define BSTR    144

__global__ __launch_bounds__(512, 1) void k3(const float* __restrict__ bv,
                                             float* __restrict__ out) {
    extern __shared__ char sm[];
    uint32_t sb = smem_u32(sm);
    int t = threadIdx.x, wid = t >> 5, l = t & 31;
    int g = wid >> 3, w8 = wid & 7, rb = w8 & 3, cb = w8 >> 2;
    int u = t & 255;
    int blk = blockIdx.x, b = blk >> 5, st = blk & 31;
    __half* sbias16 = (__half*)(sm + SM_BIAS);
    float*  sred    = (float*)(sm + SM_RED);
    __half* sdot16  = (__half*)(sm + SM_DOT);
    float*  sZf     = (float*)(sm + SM_Z);

    // A load (fp16 image), 512 threads x 256B
    {
        const char* src = (const char*)g_ximg + (size_t)(b * 4096 + st * 128) * 1024;
        int r = t >> 2, q = t & 3;
        uint32_t dst = sb + SM_A + r * ASTR + q * 256;
        const char* s = src + r * 1024 + q * 256;
        #pragma unroll
        for (int j = 0; j < 16; j++) CPASYNC16(dst + j * 16, s + j * 16);
    }
    CPCOMMIT();
    const char* bbase = (const char*)g_bhalf;
    {   // prefetch chunks 0,1 of this group's k-range (slot 16 = pseudo)
        int row = u >> 1, hf = u & 1;
        #pragma unroll
        for (int c = 0; c < 2; c++) {
            const char* s = bbase + ((size_t)(16 * 512 + g * 256 + c * 128 + row) * 64 + hf * 32) * 2;
            uint32_t d = sb + SM_B + (g * 2 + c) * SM_BCH + row * BSTR + hf * 64;
            #pragma unroll
            for (int j = 0; j < 4; j++) CPASYNC16(d + j * 16, s + j * 16);
            CPCOMMIT();
        }
    }
    for (int i = t; i < 1024; i += 512) sbias16[i] = __float2half_rn(bv[i]);
    if (t < 16) sZf[t] = 0.f;

    uint32_t a_base = sb + SM_A + (rb * 32 + (l & 7) + 8 * ((l >> 3) & 1)) * ASTR
                    + (l >> 4) * 16 + g * 512;
    uint32_t b_lane = ((l & 7) + 8 * ((l >> 3) & 1)) * BSTR + (cb * 32 + 8 * (l >> 4)) * 2;
    float acc[2][4][4];

    for (int i = 0; i < 34; i++) {
        int c = i & 1;
        uint32_t bbuf = sb + SM_B + (g * 2 + c) * SM_BCH;
        CPWAIT1();
        if (i == 0) __syncthreads();
        else BARSYNC(1 + g);
        if (c == 0) {
            #pragma unroll
            for (int m = 0; m < 2; m++)
                #pragma unroll
                for (int n = 0; n < 4; n++)
                    #pragma unroll
                    for (int e = 0; e < 4; e++) acc[m][n][e] = 0.f;
        }
        #pragma unroll
        for (int kk = 0; kk < 8; kk++) {
            uint32_t a0[4], a1[4], bf0[4], bf1[4];
            uint32_t ko = c * 256 + kk * 32;
            ldsm4(a0, a_base + ko);
            ldsm4(a1, a_base + 16 * ASTR + ko);
            uint32_t brow = bbuf + b_lane + kk * 16 * BSTR;
            ldsm4t(bf0, brow);
            ldsm4t(bf1, brow + 32);
            #pragma unroll
            for (int n = 0; n < 2; n++) {
                mma16816(acc[0][n],     a0, bf0[2 * n], bf0[2 * n + 1]);
                mma16816(acc[1][n],     a1, bf0[2 * n], bf0[2 * n + 1]);
                mma16816(acc[0][n + 2], a0, bf1[2 * n], bf1[2 * n + 1]);
                mma16816(acc[1][n + 2], a1, bf1[2 * n], bf1[2 * n + 1]);
            }
        }
        BARSYNC(1 + g);            // group done reading buffer
        if (i + 2 < 34) {
            int i2 = i + 2;
            int slot2 = (i2 < 2) ? 16 : ((i2 - 2) >> 1);
            int c2 = i2 & 1;
            int row = u >> 1, hf = u & 1;
            const char* s = bbase + ((size_t)(slot2 * 512 + g * 256 + c2 * 128 + row) * 64 + hf * 32) * 2;
            uint32_t d = sb + SM_B + (g * 2 + c2) * SM_BCH + row * BSTR + hf * 64;
            #pragma unroll
            for (int j = 0; j < 4; j++) CPASYNC16(d + j * 16, s + j * 16);
        }
        CPCOMMIT();

        if (c == 1) {                       // head end
            int hIdx = (i == 1) ? -1 : ((i - 2) >> 1);
            int owner = (i == 1) ? 0 : (1 - (hIdx & 1));
            if (g != owner) {
                // dumper: write partial-y (fp16) then non-blocking arrive
                #pragma unroll
                for (int m = 0; m < 2; m++) {
                    int rA = rb * 32 + 16 * m + (l >> 2);
                    #pragma unroll
                    for (int n = 0; n < 4; n++) {
                        int c0 = cb * 32 + 8 * n + 2 * (l & 3);
                        *(uint32_t*)(sm + SM_Y + rA * YSTR + c0 * 2) =
                            h2u(__floats2half2_rn(acc[m][n][0], acc[m][n][1]));
                        *(uint32_t*)(sm + SM_Y + (rA + 8) * YSTR + c0 * 2) =
                            h2u(__floats2half2_rn(acc[m][n][2], acc[m][n][3]));
                    }
                }
                BAR_ARRIVE4();              // owner may read; dumper streams on
            } else {
                BAR_SYNC4();                // partial-y ready
                if (hIdx < 0) {
                    // pseudo-head: dot -> exp weights + Z partials (cols 0-15 only)
                    if (w8 < 4) {
                        #pragma unroll
                        for (int m = 0; m < 2; m++) {
                            int rA = rb * 32 + 16 * m + (l >> 2);
                            #pragma unroll
                            for (int n = 0; n < 2; n++) {
                                int c0 = 8 * n + 2 * (l & 3);
                                float2 fA = __half22float2(*(const __half2*)(sm + SM_Y + rA * YSTR + c0 * 2));
                                float2 fB = __half22float2(*(const __half2*)(sm + SM_Y + (rA + 8) * YSTR + c0 * 2));
                                __half h0 = __float2half_rn(exp_fast(acc[m][n][0] + fA.x));
                                __half h1 = __float2half_rn(exp_fast(acc[m][n][1] + fA.y));
                                __half h2 = __float2half_rn(exp_fast(acc[m][n][2] + fB.x));
                                __half h3 = __float2half_rn(exp_fast(acc[m][n][3] + fB.y));
                                sdot16[rA * 16 + c0] = h0;
                                sdot16[rA * 16 + c0 + 1] = h1;
                                sdot16[(rA + 8) * 16 + c0] = h2;
                                sdot16[(rA + 8) * 16 + c0 + 1] = h3;
                                atomicAdd(&sZf[c0],     __half2float(h0) + __half2float(h2));
                                atomicAdd(&sZf[c0 + 1], __half2float(h1) + __half2float(h3));
                            }
                        }
                    }
                    BARSYNC(5 + g);
                    if (u < 16) atomicAdd(&g_Z[b * 16 + u], sZf[u]);
                } else {
                    // normal head: combine + bias + tanh + weight + reduce
                    float s0[4], s1[4];
                    #pragma unroll
                    for (int n = 0; n < 4; n++) { s0[n] = 0.f; s1[n] = 0.f; }
                    #pragma unroll
                    for (int m = 0; m < 2; m++) {
                        int rA = rb * 32 + 16 * m + (l >> 2);
                        float wA = __half2float(sdot16[rA * 16 + hIdx]);
                        float wB = __half2float(sdot16[(rA + 8) * 16 + hIdx]);
                        #pragma unroll
                        for (int n = 0; n < 4; n++) {
                            int c0 = cb * 32 + 8 * n + 2 * (l & 3);
                            float2 fA = __half22float2(*(const __half2*)(sm + SM_Y + rA * YSTR + c0 * 2));
                            float2 fB = __half22float2(*(const __half2*)(sm + SM_Y + (rA + 8) * YSTR + c0 * 2));
                            float2 bf = __half22float2(*(const __half2*)(sbias16 + hIdx * 64 + c0));
                            s0[n] += wA * tanh_fast(acc[m][n][0] + fA.x + bf.x)
                                   + wB * tanh_fast(acc[m][n][2] + fB.x + bf.x);
                            s1[n] += wA * tanh_fast(acc[m][n][1] + fA.y + bf.y)
                                   + wB * tanh_fast(acc[m][n][3] + fB.y + bf.y);
                        }
                    }
                    #pragma unroll
                    for (int o = 4; o < 32; o <<= 1)
                        #pragma unroll
                        for (int n = 0; n < 4; n++) {
                            s0[n] += __shfl_xor_sync(~0u, s0[n], o);
                            s1[n] += __shfl_xor_sync(~0u, s1[n], o);
                        }
                    if (l < 4) {
                        #pragma unroll
                        for (int n = 0; n < 4; n++) {
                            sred[w8 * 32 + 8 * n + 2 * l]     = s0[n];
                            sred[w8 * 32 + 8 * n + 2 * l + 1] = s1[n];
                        }
                    }
                    BARSYNC(5 + g);
                    if (u < 64) {
                        int cw = u >> 5, cc = u & 31;
                        float s = sred[(cw * 4 + 0) * 32 + cc] + sred[(cw * 4 + 1) * 32 + cc]
                                + sred[(cw * 4 + 2) * 32 + cc] + sred[(cw * 4 + 3) * 32 + cc];
                        atomicAdd(&out[b * 1024 + hIdx * 64 + u], s);
                    }
                }
            }
        }
    }
}

// ---------------- k4: normalize ----------------
__global__ void k4(float* __restrict__ out) {
    int id = blockIdx.x * 256 + threadIdx.x;
    out[id] = out[id] / g_Z[id >> 6];
}

// ---------------- launch ----------------
extern "C" void kernel_launch(void* const* d_in, const int* in_sizes, int n_in,
                              void* d_out, int out_size) {
    const float* kv = (const float*)d_in[0];
    const float* Wk = (const float*)d_in[1];
    const float* Wv = (const float*)d_in[3];
    const float* bv = (const float*)d_in[4];
    const float* q  = (const float*)d_in[5];
    float* out = (float*)d_out;
    cudaFuncSetAttribute(k3, cudaFuncAttributeMaxDynamicSharedMemorySize, K3_DYN);
    kA<<<162, 256>>>(Wk, q, out);
    kB<<<2176, 256>>>(Wv);
    kconv<<<16384, 256>>>(kv);
    k3<<<1024, 512, K3_DYN>>>(bv, out);
    k4<<<128, 256>>>(out);
}